// round 8
// baseline (speedup 1.0000x reference)
#include <cuda_runtime.h>
#include <cuda_fp16.h>
#include <math.h>
#include <stdint.h>

#define NPTS 8192
#define DIM 256
#define KC 64
#define NCHUNK (DIM / KC)
#define RPB 4
#define SM_SOFTMIN (RPB * 16384)   // 64 KB staged G / lists
#define CAP 4096                   // max shortlist entries per row (16KB packed)
#define MARGIN 0.08f

// ---------------- static device scratch (no allocation allowed) ----------------
__device__ float  d_wc[DIM];
__device__ __half d_anh[(size_t)NPTS * DIM];
__device__ __half d_bnh[(size_t)NPTS * DIM];
__device__ __half d_Gxy[(size_t)NPTS * NPTS];
__device__ __half d_Gyx[(size_t)NPTS * NPTS];
__device__ __half d_Gxx[(size_t)NPTS * NPTS];
__device__ __half d_Gyy[(size_t)NPTS * NPTS];
__device__ float  d_f[2][NPTS];
__device__ float  d_g[2][NPTS];
__device__ float  d_fxx[2][NPTS];
__device__ float  d_gyy[2][NPTS];
__device__ float  d_ffin[NPTS], d_gfin[NPTS], d_xfin[NPTS], d_yfin[NPTS];
// sparse shortlist machinery (variant: 0=Gxx,1=Gyy,2=Gxy,3=Gyx)
__device__ uint32_t d_list[4][NPTS][CAP];   // packed {col<<16 | halfbits}
__device__ int      d_cnt[4][NPTS];         // -1 => dense row
__device__ float    d_delta[4];             // build threshold width
__device__ float    d_sprd[4];              // live pot spread

__device__ __forceinline__ float ex2f_fast(float x) {
    float y; asm("ex2.approx.ftz.f32 %0, %1;" : "=f"(y) : "f"(x)); return y;
}
__device__ __forceinline__ uint32_t smem_u32(const void* p) {
    uint32_t a;
    asm("{ .reg .u64 t; cvta.to.shared.u64 t, %1; cvt.u32.u64 %0, t; }" : "=r"(a) : "l"(p));
    return a;
}
__device__ __forceinline__ void cp_async16(uint32_t dst, const void* src) {
    asm volatile("cp.async.cg.shared.global [%0], [%1], 16;" :: "r"(dst), "l"(src) : "memory");
}
#define LDMX4(r, addr)                                                          \
    asm volatile("ldmatrix.sync.aligned.m8n8.x4.shared.b16 {%0,%1,%2,%3}, [%4];" \
                 : "=r"((r)[0]), "=r"((r)[1]), "=r"((r)[2]), "=r"((r)[3])        \
                 : "r"(addr))

// ---------------- prep ----------------
__global__ void wprep_kernel(const float* __restrict__ w) {
    __shared__ float sh[DIM];
    int t = threadIdx.x;
    float c = fminf(fmaxf(w[t], 0.0f), 2.0f);
    sh[t] = c;
    __syncthreads();
    for (int off = DIM / 2; off > 0; off >>= 1) {
        if (t < off) sh[t] += sh[t + off];
        __syncthreads();
    }
    d_wc[t] = c * ((float)DIM / sh[0]);
}

__global__ void rownorm_kernel(const float* __restrict__ x1, const float* __restrict__ x2) {
    __shared__ float sh[DIM];
    int b = blockIdx.x, t = threadIdx.x;
    float v;
    if (b < NPTS) v = d_wc[t] * x1[(size_t)b * DIM + t];
    else          v = x2[(size_t)(b - NPTS) * DIM + t];
    sh[t] = v * v;
    __syncthreads();
    for (int off = DIM / 2; off > 0; off >>= 1) {
        if (t < off) sh[t] += sh[t + off];
        __syncthreads();
    }
    float inv = 1.0f / (sqrtf(sh[0]) + 1e-12f);
    __half h = __float2half_rn(v * inv);
    if (b < NPTS) d_anh[(size_t)b * DIM + t] = h;
    else          d_bnh[(size_t)(b - NPTS) * DIM + t] = h;
}

__global__ void zero_kernel() {
    int i = blockIdx.x * blockDim.x + threadIdx.x;
    if (i < NPTS) {
        d_f[0][i] = 0.0f; d_g[0][i] = 0.0f;
        d_fxx[0][i] = 0.0f; d_gyy[0][i] = 0.0f;
    }
}

// ---------------- HMMA GEMM: C = A * B^T (+ transposed output CT) ----------------
__global__ void __launch_bounds__(256, 2) gemm_mma(const __half* __restrict__ A,
                                                   const __half* __restrict__ B,
                                                   __half* __restrict__ C,
                                                   __half* __restrict__ CT,
                                                   int sym) {
    extern __shared__ char smem[];
    const int btx = blockIdx.x, bty = blockIdx.y;
    if (sym && btx > bty) return;

    const uint32_t smem_base = smem_u32(smem);
    const int tid = threadIdx.x;
    const int wid = tid >> 5, lane = tid & 31;
    const int warp_m = wid >> 2, warp_n = wid & 3;
    const int rowBase = bty * 128;
    const int colBase = btx * 128;

    const int mat = lane >> 3, rin = lane & 7;
    const int a_row_in = (mat & 1) * 8 + rin;
    const int a_kh     = (mat >> 1) * 8;
    const int b_row_in = (mat >> 1) * 8 + rin;
    const int b_kh     = (mat & 1) * 8;

    float acc[4][4][4];
#pragma unroll
    for (int mi = 0; mi < 4; ++mi)
#pragma unroll
        for (int ni = 0; ni < 4; ++ni)
#pragma unroll
            for (int q = 0; q < 4; ++q) acc[mi][ni][q] = 0.0f;

#define ISSUE_CHUNK(c, b) do {                                                  \
        const __half* Asrc_ = A + (size_t)rowBase * DIM + (c) * KC;             \
        const __half* Bsrc_ = B + (size_t)colBase * DIM + (c) * KC;             \
        uint32_t Ab_ = smem_base + (b) * 32768;                                 \
        uint32_t Bb_ = Ab_ + 16384;                                             \
        _Pragma("unroll")                                                       \
        for (int q_ = 0; q_ < 4; ++q_) {                                        \
            int i_ = q_ * 256 + tid;                                            \
            int r_ = i_ >> 3, cw_ = i_ & 7;                                     \
            uint32_t off_ = r_ * 128 + (((uint32_t)(cw_ ^ (r_ & 7))) << 4);     \
            cp_async16(Ab_ + off_, Asrc_ + (size_t)r_ * DIM + cw_ * 8);         \
            cp_async16(Bb_ + off_, Bsrc_ + (size_t)r_ * DIM + cw_ * 8);         \
        }                                                                       \
        asm volatile("cp.async.commit_group;" ::: "memory");                    \
    } while (0)

    ISSUE_CHUNK(0, 0);
#pragma unroll
    for (int c = 0; c < NCHUNK; ++c) {
        if (c + 1 < NCHUNK) {
            ISSUE_CHUNK(c + 1, (c + 1) & 1);
            asm volatile("cp.async.wait_group 1;" ::: "memory");
        } else {
            asm volatile("cp.async.wait_group 0;" ::: "memory");
        }
        __syncthreads();
        uint32_t Ab = smem_base + (c & 1) * 32768;
        uint32_t Bb = Ab + 16384;
#pragma unroll
        for (int ks = 0; ks < 4; ++ks) {
            uint32_t bf[2][4];
#pragma unroll
            for (int p = 0; p < 2; ++p) {
                int nrow = warp_n * 32 + p * 16 + b_row_in;
                int kcol = ks * 16 + b_kh;
                uint32_t addr = Bb + nrow * 128 + ((uint32_t)((kcol >> 3) ^ (nrow & 7)) << 4);
                LDMX4(bf[p], addr);
            }
#pragma unroll
            for (int mi = 0; mi < 4; ++mi) {
                uint32_t af[4];
                int arow = warp_m * 64 + mi * 16 + a_row_in;
                int kcol = ks * 16 + a_kh;
                uint32_t addr = Ab + arow * 128 + ((uint32_t)((kcol >> 3) ^ (arow & 7)) << 4);
                LDMX4(af, addr);
#pragma unroll
                for (int ni = 0; ni < 4; ++ni) {
                    asm volatile(
                        "mma.sync.aligned.m16n8k16.row.col.f32.f16.f16.f32 "
                        "{%0,%1,%2,%3}, {%4,%5,%6,%7}, {%8,%9}, {%0,%1,%2,%3};"
                        : "+f"(acc[mi][ni][0]), "+f"(acc[mi][ni][1]),
                          "+f"(acc[mi][ni][2]), "+f"(acc[mi][ni][3])
                        : "r"(af[0]), "r"(af[1]), "r"(af[2]), "r"(af[3]),
                          "r"(bf[ni >> 1][(ni & 1) * 2]), "r"(bf[ni >> 1][(ni & 1) * 2 + 1]));
                }
            }
        }
        __syncthreads();
    }
#undef ISSUE_CHUNK

    __half* stage = (__half*)smem;
#pragma unroll
    for (int mi = 0; mi < 4; ++mi)
#pragma unroll
        for (int ni = 0; ni < 4; ++ni) {
            int row = warp_m * 64 + mi * 16 + (lane >> 2);
            int col = warp_n * 32 + ni * 8 + 2 * (lane & 3);
            __half2 lo = __floats2half2_rn(acc[mi][ni][0], acc[mi][ni][1]);
            __half2 hi = __floats2half2_rn(acc[mi][ni][2], acc[mi][ni][3]);
            *(__half2*)(stage + row * 136 + col)       = lo;
            *(__half2*)(stage + (row + 8) * 136 + col) = hi;
        }
    __syncthreads();
#pragma unroll
    for (int i = tid; i < 2048; i += 256) {
        int r = i >> 4, ch = i & 15;
        uint4 v = *(uint4*)(stage + r * 136 + ch * 8);
        *(uint4*)(C + (size_t)(rowBase + r) * NPTS + colBase + ch * 8) = v;
    }

    if (!(sym && btx == bty)) {
        __syncthreads();
#pragma unroll
        for (int mi = 0; mi < 4; ++mi)
#pragma unroll
            for (int ni = 0; ni < 4; ++ni) {
                int row = warp_m * 64 + mi * 16 + (lane >> 2);
                int col = warp_n * 32 + ni * 8 + 2 * (lane & 3);
                stage[col * 136 + row]           = __float2half_rn(acc[mi][ni][0]);
                stage[(col + 1) * 136 + row]     = __float2half_rn(acc[mi][ni][1]);
                stage[col * 136 + row + 8]       = __float2half_rn(acc[mi][ni][2]);
                stage[(col + 1) * 136 + row + 8] = __float2half_rn(acc[mi][ni][3]);
            }
        __syncthreads();
#pragma unroll
        for (int i = tid; i < 2048; i += 256) {
            int r = i >> 4, ch = i & 15;
            uint4 v = *(uint4*)(stage + r * 136 + ch * 8);
            *(uint4*)(CT + (size_t)(colBase + r) * NPTS + rowBase + ch * 8) = v;
        }
    }
}

// ---------------- dense softmin (iterations at large eps) ----------------
struct SMArgs {
    const __half* G[4];
    const float*  pot[4];
    const float*  oldpot[4];
    float*        out[4];
    int           avg[4];
};

__global__ void __launch_bounds__(256) softmin4(SMArgs args, float eps) {
    extern __shared__ char smg[];
    const uint32_t smg_u = smem_u32(smg);
    const int var  = blockIdx.y;
    const int row0 = blockIdx.x * RPB;
    const int tid  = threadIdx.x;
    const int lane = tid & 31, wid = tid >> 5;

    const float L2E = 1.4426950408889634f;
    const float c1 = L2E / eps;
    const float c0 = -c1;

    const __half* Gbase = args.G[var];
#pragma unroll
    for (int r = 0; r < RPB; ++r) {
        const __half* Gr = Gbase + (size_t)(row0 + r) * NPTS;
#pragma unroll
        for (int q = 0; q < 4; ++q) {
            int idx = q * 256 + tid;
            cp_async16(smg_u + r * 16384 + idx * 16, Gr + idx * 8);
        }
    }
    asm volatile("cp.async.commit_group;" ::: "memory");

    const float* pot = args.pot[var];
    float pp[32];
#pragma unroll
    for (int it = 0; it < 4; ++it) {
        int idx = it * 256 + tid;
        float4 a = ((const float4*)pot)[2 * idx];
        float4 b = ((const float4*)pot)[2 * idx + 1];
        pp[8 * it + 0] = fmaf(a.x, c1, c0); pp[8 * it + 1] = fmaf(a.y, c1, c0);
        pp[8 * it + 2] = fmaf(a.z, c1, c0); pp[8 * it + 3] = fmaf(a.w, c1, c0);
        pp[8 * it + 4] = fmaf(b.x, c1, c0); pp[8 * it + 5] = fmaf(b.y, c1, c0);
        pp[8 * it + 6] = fmaf(b.z, c1, c0); pp[8 * it + 7] = fmaf(b.w, c1, c0);
    }

    asm volatile("cp.async.wait_group 0;" ::: "memory");

    __shared__ float sA[RPB][8];
    __shared__ float sS[RPB][8];

    float wtm[RPB];
#pragma unroll
    for (int r = 0; r < RPB; ++r) {
        float tm = -INFINITY;
#pragma unroll
        for (int it = 0; it < 4; ++it) {
            uint4 q = *(const uint4*)(smg + r * 16384 + (it * 256 + tid) * 16);
            float2 g0 = __half22float2(*(const __half2*)&q.x);
            float2 g1 = __half22float2(*(const __half2*)&q.y);
            float2 g2 = __half22float2(*(const __half2*)&q.z);
            float2 g3 = __half22float2(*(const __half2*)&q.w);
            float v0 = fmaf(g0.x, c1, pp[8 * it + 0]);
            float v1 = fmaf(g0.y, c1, pp[8 * it + 1]);
            float v2 = fmaf(g1.x, c1, pp[8 * it + 2]);
            float v3 = fmaf(g1.y, c1, pp[8 * it + 3]);
            float v4 = fmaf(g2.x, c1, pp[8 * it + 4]);
            float v5 = fmaf(g2.y, c1, pp[8 * it + 5]);
            float v6 = fmaf(g3.x, c1, pp[8 * it + 6]);
            float v7 = fmaf(g3.y, c1, pp[8 * it + 7]);
            tm = fmaxf(tm, fmaxf(fmaxf(fmaxf(v0, v1), fmaxf(v2, v3)),
                                 fmaxf(fmaxf(v4, v5), fmaxf(v6, v7))));
        }
#pragma unroll
        for (int off = 16; off > 0; off >>= 1)
            tm = fmaxf(tm, __shfl_xor_sync(0xffffffffu, tm, off));
        wtm[r] = tm;
        if (lane == 0) sA[r][wid] = tm;
    }
    __syncthreads();
    float M[RPB];
#pragma unroll
    for (int r = 0; r < RPB; ++r) {
        float m = sA[r][0];
#pragma unroll
        for (int i = 1; i < 8; ++i) m = fmaxf(m, sA[r][i]);
        M[r] = m;
    }

#pragma unroll
    for (int r = 0; r < RPB; ++r) {
        float s = 0.0f;
        if (wtm[r] >= M[r] - 40.0f) {
            float Mr = M[r];
            float s0 = 0.f, s1 = 0.f, s2 = 0.f, s3 = 0.f;
#pragma unroll
            for (int it = 0; it < 4; ++it) {
                uint4 q = *(const uint4*)(smg + r * 16384 + (it * 256 + tid) * 16);
                float2 g0 = __half22float2(*(const __half2*)&q.x);
                float2 g1 = __half22float2(*(const __half2*)&q.y);
                float2 g2 = __half22float2(*(const __half2*)&q.z);
                float2 g3 = __half22float2(*(const __half2*)&q.w);
                s0 += ex2f_fast(fmaf(g0.x, c1, pp[8 * it + 0]) - Mr);
                s1 += ex2f_fast(fmaf(g0.y, c1, pp[8 * it + 1]) - Mr);
                s2 += ex2f_fast(fmaf(g1.x, c1, pp[8 * it + 2]) - Mr);
                s3 += ex2f_fast(fmaf(g1.y, c1, pp[8 * it + 3]) - Mr);
                s0 += ex2f_fast(fmaf(g2.x, c1, pp[8 * it + 4]) - Mr);
                s1 += ex2f_fast(fmaf(g2.y, c1, pp[8 * it + 5]) - Mr);
                s2 += ex2f_fast(fmaf(g3.x, c1, pp[8 * it + 6]) - Mr);
                s3 += ex2f_fast(fmaf(g3.y, c1, pp[8 * it + 7]) - Mr);
            }
            s = (s0 + s1) + (s2 + s3);
        }
#pragma unroll
        for (int off = 16; off > 0; off >>= 1)
            s += __shfl_xor_sync(0xffffffffu, s, off);
        if (lane == 0) sS[r][wid] = s;
    }
    __syncthreads();

    if (tid < RPB) {
        int r = tid;
        float S = ((sS[r][0] + sS[r][1]) + (sS[r][2] + sS[r][3]))
                + ((sS[r][4] + sS[r][5]) + (sS[r][6] + sS[r][7]));
        const float LOGW = -9.010913347279288f;
        const float LN2  = 0.6931471805599453f;
        float lse = (M[r] + log2f(S)) * LN2;
        float res = -eps * (LOGW + lse);
        if (args.avg[var]) res = 0.5f * (args.oldpot[var][row0 + r] + res);
        args.out[var][row0 + r] = res;
    }
}

// ---------------- pot spread (max - min) per variant ----------------
__global__ void spread_kernel(const float* p0, const float* p1,
                              const float* p2, const float* p3, int store_delta) {
    const float* p = (blockIdx.x == 0) ? p0 : (blockIdx.x == 1) ? p1
                   : (blockIdx.x == 2) ? p2 : p3;
    __shared__ float smx[256], smn[256];
    int t = threadIdx.x;
    float mx = -INFINITY, mn = INFINITY;
    for (int i = t; i < NPTS; i += 256) {
        float v = p[i];
        mx = fmaxf(mx, v); mn = fminf(mn, v);
    }
    smx[t] = mx; smn[t] = mn;
    __syncthreads();
    for (int off = 128; off > 0; off >>= 1) {
        if (t < off) {
            smx[t] = fmaxf(smx[t], smx[t + off]);
            smn[t] = fminf(smn[t], smn[t + off]);
        }
        __syncthreads();
    }
    if (t == 0) {
        float s = smx[0] - smn[0];
        d_sprd[blockIdx.x] = s;
        if (store_delta) d_delta[blockIdx.x] = 0.069314718f + s + MARGIN;
    }
}

// ---------------- shortlist build (per-row, per-matrix) ----------------
struct BArgs { const __half* G[4]; };

__global__ void __launch_bounds__(256) build_kernel(BArgs args) {
    extern __shared__ char smg[];
    const uint32_t smg_u = smem_u32(smg);
    const int var  = blockIdx.y;
    const int row0 = blockIdx.x * RPB;
    const int tid  = threadIdx.x;
    const int lane = tid & 31, wid = tid >> 5;

    const __half* Gbase = args.G[var];
#pragma unroll
    for (int r = 0; r < RPB; ++r) {
        const __half* Gr = Gbase + (size_t)(row0 + r) * NPTS;
#pragma unroll
        for (int q = 0; q < 4; ++q) {
            int idx = q * 256 + tid;
            cp_async16(smg_u + r * 16384 + idx * 16, Gr + idx * 8);
        }
    }
    asm volatile("cp.async.commit_group;" ::: "memory");
    asm volatile("cp.async.wait_group 0;" ::: "memory");
    __syncthreads();

    const float delta = d_delta[var];
    __shared__ float sA[8];
    __shared__ int   sPfx[256];

    for (int r = 0; r < RPB; ++r) {
        const int row = row0 + r;
        // pass 1: row max of G
        float tm = -INFINITY;
#pragma unroll
        for (int it = 0; it < 4; ++it) {
            uint4 q = *(const uint4*)(smg + r * 16384 + (it * 256 + tid) * 16);
            float2 g0 = __half22float2(*(const __half2*)&q.x);
            float2 g1 = __half22float2(*(const __half2*)&q.y);
            float2 g2 = __half22float2(*(const __half2*)&q.z);
            float2 g3 = __half22float2(*(const __half2*)&q.w);
            tm = fmaxf(tm, fmaxf(fmaxf(fmaxf(g0.x, g0.y), fmaxf(g1.x, g1.y)),
                                 fmaxf(fmaxf(g2.x, g2.y), fmaxf(g3.x, g3.y))));
        }
#pragma unroll
        for (int off = 16; off > 0; off >>= 1)
            tm = fmaxf(tm, __shfl_xor_sync(0xffffffffu, tm, off));
        if (lane == 0) sA[wid] = tm;
        __syncthreads();
        float maxG = sA[0];
#pragma unroll
        for (int i = 1; i < 8; ++i) maxG = fmaxf(maxG, sA[i]);
        const float thr = maxG - delta;

        // pass 2: per-thread count of selected entries
        int cnt = 0;
#pragma unroll
        for (int it = 0; it < 4; ++it) {
            uint4 q = *(const uint4*)(smg + r * 16384 + (it * 256 + tid) * 16);
            const uint32_t w[4] = {q.x, q.y, q.z, q.w};
#pragma unroll
            for (int k = 0; k < 4; ++k) {
                float2 g = __half22float2(*(const __half2*)&w[k]);
                cnt += (g.x >= thr) + (g.y >= thr);
            }
        }
        __syncthreads();              // sA reuse guard
        sPfx[tid] = cnt;
        __syncthreads();
        for (int off = 1; off < 256; off <<= 1) {
            int v = (tid >= off) ? sPfx[tid - off] : 0;
            __syncthreads();
            sPfx[tid] += v;
            __syncthreads();
        }
        int excl = sPfx[tid] - cnt;
        int total = sPfx[255];

        // pass 3: write packed entries
        if (total <= CAP) {
            uint32_t* dst = &d_list[var][row][0];
            int o = excl;
#pragma unroll
            for (int it = 0; it < 4; ++it) {
                int chunk = it * 256 + tid;
                uint4 q = *(const uint4*)(smg + r * 16384 + chunk * 16);
                const uint32_t w[4] = {q.x, q.y, q.z, q.w};
                int colb = chunk * 8;
#pragma unroll
                for (int k = 0; k < 4; ++k) {
                    float2 g = __half22float2(*(const __half2*)&w[k]);
                    if (g.x >= thr) dst[o++] = ((uint32_t)(colb + 2 * k) << 16) | (w[k] & 0xFFFFu);
                    if (g.y >= thr) dst[o++] = ((uint32_t)(colb + 2 * k + 1) << 16) | (w[k] >> 16);
                }
            }
        }
        if (tid == 0) d_cnt[var][row] = (total <= CAP) ? total : -1;
        __syncthreads();
    }
}

// ---------------- sparse softmin (eps = 0.0025 launches) ----------------
__global__ void __launch_bounds__(256) softmin4_sparse(SMArgs args, float eps) {
    extern __shared__ char smg[];
    const uint32_t smg_u = smem_u32(smg);
    const int var  = blockIdx.y;
    const int row0 = blockIdx.x * RPB;
    const int tid  = threadIdx.x;
    const int lane = tid & 31, wid = tid >> 5;

    const float L2E = 1.4426950408889634f;
    const float c1 = L2E / eps;
    const float c0 = -c1;
    const float need = 40.0f * eps * 0.6931471805599453f;   // 40/c1
    const bool valid = (d_sprd[var] + need <= d_delta[var]);

    const __half* Gbase = args.G[var];
    const float*  pot   = args.pot[var];

    int  cnt[RPB];
    bool dense[RPB];
#pragma unroll
    for (int r = 0; r < RPB; ++r) {
        int row = row0 + r;
        int c = d_cnt[var][row];
        dense[r] = (!valid) || (c < 0);
        cnt[r] = c;
        if (dense[r]) {
            const __half* Gr = Gbase + (size_t)row * NPTS;
#pragma unroll
            for (int q = 0; q < 4; ++q) {
                int idx = q * 256 + tid;
                cp_async16(smg_u + r * 16384 + idx * 16, Gr + idx * 8);
            }
        } else {
            const uint32_t* Lr = &d_list[var][row][0];
            int nch = (c + 3) >> 2;
            for (int i = tid; i < nch; i += 256)
                cp_async16(smg_u + r * 16384 + i * 16, Lr + i * 4);
        }
    }
    asm volatile("cp.async.commit_group;" ::: "memory");
    asm volatile("cp.async.wait_group 0;" ::: "memory");
    __syncthreads();

    __shared__ float sA[8];

    for (int r = 0; r < RPB; ++r) {
        const int row = row0 + r;
        float tm = -INFINITY;
        if (dense[r]) {
#pragma unroll
            for (int it = 0; it < 4; ++it) {
                int chunk = it * 256 + tid;
                uint4 q = *(const uint4*)(smg + r * 16384 + chunk * 16);
                float4 pa = __ldg((const float4*)(pot + chunk * 8));
                float4 pb = __ldg((const float4*)(pot + chunk * 8 + 4));
                float2 g0 = __half22float2(*(const __half2*)&q.x);
                float2 g1 = __half22float2(*(const __half2*)&q.y);
                float2 g2 = __half22float2(*(const __half2*)&q.z);
                float2 g3 = __half22float2(*(const __half2*)&q.w);
                float v0 = fmaf(g0.x + pa.x, c1, c0);
                float v1 = fmaf(g0.y + pa.y, c1, c0);
                float v2 = fmaf(g1.x + pa.z, c1, c0);
                float v3 = fmaf(g1.y + pa.w, c1, c0);
                float v4 = fmaf(g2.x + pb.x, c1, c0);
                float v5 = fmaf(g2.y + pb.y, c1, c0);
                float v6 = fmaf(g3.x + pb.z, c1, c0);
                float v7 = fmaf(g3.y + pb.w, c1, c0);
                tm = fmaxf(tm, fmaxf(fmaxf(fmaxf(v0, v1), fmaxf(v2, v3)),
                                     fmaxf(fmaxf(v4, v5), fmaxf(v6, v7))));
            }
        } else {
            for (int e = tid; e < cnt[r]; e += 256) {
                uint32_t p = *(const uint32_t*)(smg + r * 16384 + e * 4);
                float g = __half2float(__ushort_as_half((unsigned short)(p & 0xFFFFu)));
                float u = fmaf(g + __ldg(pot + (p >> 16)), c1, c0);
                tm = fmaxf(tm, u);
            }
        }
#pragma unroll
        for (int off = 16; off > 0; off >>= 1)
            tm = fmaxf(tm, __shfl_xor_sync(0xffffffffu, tm, off));
        float wtm = tm;
        if (lane == 0) sA[wid] = tm;
        __syncthreads();
        float M = sA[0];
#pragma unroll
        for (int i = 1; i < 8; ++i) M = fmaxf(M, sA[i]);
        __syncthreads();

        float s = 0.0f;
        if (dense[r]) {
            if (wtm >= M - 40.0f) {
                float s0 = 0.f, s1 = 0.f;
#pragma unroll
                for (int it = 0; it < 4; ++it) {
                    int chunk = it * 256 + tid;
                    uint4 q = *(const uint4*)(smg + r * 16384 + chunk * 16);
                    float4 pa = __ldg((const float4*)(pot + chunk * 8));
                    float4 pb = __ldg((const float4*)(pot + chunk * 8 + 4));
                    float2 g0 = __half22float2(*(const __half2*)&q.x);
                    float2 g1 = __half22float2(*(const __half2*)&q.y);
                    float2 g2 = __half22float2(*(const __half2*)&q.z);
                    float2 g3 = __half22float2(*(const __half2*)&q.w);
                    s0 += ex2f_fast(fmaf(g0.x + pa.x, c1, c0) - M);
                    s1 += ex2f_fast(fmaf(g0.y + pa.y, c1, c0) - M);
                    s0 += ex2f_fast(fmaf(g1.x + pa.z, c1, c0) - M);
                    s1 += ex2f_fast(fmaf(g1.y + pa.w, c1, c0) - M);
                    s0 += ex2f_fast(fmaf(g2.x + pb.x, c1, c0) - M);
                    s1 += ex2f_fast(fmaf(g2.y + pb.y, c1, c0) - M);
                    s0 += ex2f_fast(fmaf(g3.x + pb.z, c1, c0) - M);
                    s1 += ex2f_fast(fmaf(g3.y + pb.w, c1, c0) - M);
                }
                s = s0 + s1;
            }
        } else {
            for (int e = tid; e < cnt[r]; e += 256) {
                uint32_t p = *(const uint32_t*)(smg + r * 16384 + e * 4);
                float g = __half2float(__ushort_as_half((unsigned short)(p & 0xFFFFu)));
                s += ex2f_fast(fmaf(g + __ldg(pot + (p >> 16)), c1, c0) - M);
            }
        }
#pragma unroll
        for (int off = 16; off > 0; off >>= 1)
            s += __shfl_xor_sync(0xffffffffu, s, off);
        if (lane == 0) sA[wid] = s;
        __syncthreads();
        if (tid == 0) {
            float S = ((sA[0] + sA[1]) + (sA[2] + sA[3]))
                    + ((sA[4] + sA[5]) + (sA[6] + sA[7]));
            const float LOGW = -9.010913347279288f;
            const float LN2  = 0.6931471805599453f;
            float lse = (M + log2f(S)) * LN2;
            float res = -eps * (LOGW + lse);
            if (args.avg[var]) res = 0.5f * (args.oldpot[var][row] + res);
            args.out[var][row] = res;
        }
        __syncthreads();
    }
}

// ---------------- final reduction ----------------
__global__ void final_reduce(float* __restrict__ out) {
    __shared__ float sh[1024];
    int t = threadIdx.x;
    float s = 0.0f;
    for (int i = t; i < NPTS; i += 1024)
        s += (d_ffin[i] - d_xfin[i]) + (d_gfin[i] - d_yfin[i]);
    sh[t] = s;
    __syncthreads();
    for (int off = 512; off > 0; off >>= 1) {
        if (t < off) sh[t] += sh[t + off];
        __syncthreads();
    }
    if (t == 0) out[0] = sh[0] / (float)NPTS;
}

// ---------------- host ----------------
static void* symaddr(const void* sym) {
    void* p = nullptr;
    cudaGetSymbolAddress(&p, sym);
    return p;
}

#define GEMM_SMEM 65536

extern "C" void kernel_launch(void* const* d_in, const int* in_sizes, int n_in,
                              void* d_out, int out_size) {
    const float* x1 = (const float*)d_in[0];
    const float* x2 = (const float*)d_in[1];
    const float* w  = (const float*)d_in[2];

    __half* an  = (__half*)symaddr(d_anh);
    __half* bn  = (__half*)symaddr(d_bnh);
    __half* Gxy = (__half*)symaddr(d_Gxy);
    __half* Gyx = (__half*)symaddr(d_Gyx);
    __half* Gxx = (__half*)symaddr(d_Gxx);
    __half* Gyy = (__half*)symaddr(d_Gyy);
    float* fb  = (float*)symaddr(d_f);
    float* gb  = (float*)symaddr(d_g);
    float* xb  = (float*)symaddr(d_fxx);
    float* yb  = (float*)symaddr(d_gyy);
    float* ffin = (float*)symaddr(d_ffin);
    float* gfin = (float*)symaddr(d_gfin);
    float* xfin = (float*)symaddr(d_xfin);
    float* yfin = (float*)symaddr(d_yfin);

    cudaFuncSetAttribute(gemm_mma, cudaFuncAttributeMaxDynamicSharedMemorySize, GEMM_SMEM);
    cudaFuncSetAttribute(softmin4, cudaFuncAttributeMaxDynamicSharedMemorySize, SM_SOFTMIN);
    cudaFuncSetAttribute(build_kernel, cudaFuncAttributeMaxDynamicSharedMemorySize, SM_SOFTMIN);
    cudaFuncSetAttribute(softmin4_sparse, cudaFuncAttributeMaxDynamicSharedMemorySize, SM_SOFTMIN);

    wprep_kernel<<<1, DIM>>>(w);
    rownorm_kernel<<<2 * NPTS, DIM>>>(x1, x2);
    zero_kernel<<<NPTS / 256, 256>>>();

    dim3 ggrid(NPTS / 128, NPTS / 128);
    gemm_mma<<<ggrid, 256, GEMM_SMEM>>>(an, bn, Gxy, Gyx, 0);
    gemm_mma<<<ggrid, 256, GEMM_SMEM>>>(an, an, Gxx, Gxx, 1);
    gemm_mma<<<ggrid, 256, GEMM_SMEM>>>(bn, bn, Gyy, Gyy, 1);

    const float eps_list[10] = {4.0f, 1.0f, 0.25f, 0.0625f, 0.015625f,
                                0.00390625f, 0.0025f, 0.0025f, 0.0025f, 0.0025f};
    dim3 sgrid(NPTS / RPB, 4);
    int cur = 0;

    // iterations 0..5: dense
    for (int i = 0; i < 6; ++i) {
        float eps = eps_list[i];
        int nxt = 1 - cur;
        SMArgs a;
        a.G[0] = Gxx;  a.pot[0] = xb + cur * NPTS; a.oldpot[0] = xb + cur * NPTS; a.out[0] = xb + nxt * NPTS; a.avg[0] = 1;
        a.G[1] = Gyy;  a.pot[1] = yb + cur * NPTS; a.oldpot[1] = yb + cur * NPTS; a.out[1] = yb + nxt * NPTS; a.avg[1] = 1;
        a.G[2] = Gxy;  a.pot[2] = gb + cur * NPTS; a.oldpot[2] = nullptr;         a.out[2] = fb + nxt * NPTS; a.avg[2] = 0;
        a.G[3] = Gyx;  a.pot[3] = fb + cur * NPTS; a.oldpot[3] = nullptr;         a.out[3] = gb + nxt * NPTS; a.avg[3] = 0;
        softmin4<<<sgrid, 256, SM_SOFTMIN>>>(a, eps);
        cur = nxt;
    }

    // build shortlists from current pots
    spread_kernel<<<4, 256>>>(xb + cur * NPTS, yb + cur * NPTS,
                              gb + cur * NPTS, fb + cur * NPTS, 1);
    {
        BArgs b;
        b.G[0] = Gxx; b.G[1] = Gyy; b.G[2] = Gxy; b.G[3] = Gyx;
        build_kernel<<<sgrid, 256, SM_SOFTMIN>>>(b);
    }

    // iterations 6..9: sparse (with dense fallback)
    for (int i = 6; i < 10; ++i) {
        float eps = eps_list[i];
        int nxt = 1 - cur;
        SMArgs a;
        a.G[0] = Gxx;  a.pot[0] = xb + cur * NPTS; a.oldpot[0] = xb + cur * NPTS; a.out[0] = xb + nxt * NPTS; a.avg[0] = 1;
        a.G[1] = Gyy;  a.pot[1] = yb + cur * NPTS; a.oldpot[1] = yb + cur * NPTS; a.out[1] = yb + nxt * NPTS; a.avg[1] = 1;
        a.G[2] = Gxy;  a.pot[2] = gb + cur * NPTS; a.oldpot[2] = nullptr;         a.out[2] = fb + nxt * NPTS; a.avg[2] = 0;
        a.G[3] = Gyx;  a.pot[3] = fb + cur * NPTS; a.oldpot[3] = nullptr;         a.out[3] = gb + nxt * NPTS; a.avg[3] = 0;
        spread_kernel<<<4, 256>>>(a.pot[0], a.pot[1], a.pot[2], a.pot[3], 0);
        softmin4_sparse<<<sgrid, 256, SM_SOFTMIN>>>(a, eps);
        cur = nxt;
    }

    // final extrapolation (same variant->matrix order as build)
    const float epsF = 0.0025f;
    {
        SMArgs a;
        a.G[0] = Gxx; a.pot[0] = xb + cur * NPTS; a.oldpot[0] = nullptr; a.out[0] = xfin; a.avg[0] = 0;
        a.G[1] = Gyy; a.pot[1] = yb + cur * NPTS; a.oldpot[1] = nullptr; a.out[1] = yfin; a.avg[1] = 0;
        a.G[2] = Gxy; a.pot[2] = gb + cur * NPTS; a.oldpot[2] = nullptr; a.out[2] = ffin; a.avg[2] = 0;
        a.G[3] = Gyx; a.pot[3] = fb + cur * NPTS; a.oldpot[3] = nullptr; a.out[3] = gfin; a.avg[3] = 0;
        spread_kernel<<<4, 256>>>(a.pot[0], a.pot[1], a.pot[2], a.pot[3], 0);
        softmin4_sparse<<<sgrid, 256, SM_SOFTMIN>>>(a, epsF);
    }

    final_reduce<<<1, 1024>>>((float*)d_out);
}

// round 9
// speedup vs baseline: 1.1557x; 1.1557x over previous
#include <cuda_runtime.h>
#include <cuda_fp16.h>
#include <math.h>
#include <stdint.h>

#define NPTS 8192
#define DIM 256
#define KC 64
#define NCHUNK (DIM / KC)
#define RPB 4
#define SOFT_T 512
#define SM_SOFTMIN (RPB * 16384)   // 64 KB staged G

// ---------------- static device scratch (no allocation allowed) ----------------
__device__ float  d_wc[DIM];
__device__ __half d_anh[(size_t)NPTS * DIM];
__device__ __half d_bnh[(size_t)NPTS * DIM];
__device__ __half d_Gxy[(size_t)NPTS * NPTS];
__device__ __half d_Gyx[(size_t)NPTS * NPTS];
__device__ __half d_Gxx[(size_t)NPTS * NPTS];
__device__ __half d_Gyy[(size_t)NPTS * NPTS];
__device__ float  d_f[2][NPTS];
__device__ float  d_g[2][NPTS];
__device__ float  d_fxx[2][NPTS];
__device__ float  d_gyy[2][NPTS];
__device__ float  d_ffin[NPTS], d_gfin[NPTS], d_xfin[NPTS], d_yfin[NPTS];

__device__ __forceinline__ float ex2f_fast(float x) {
    float y; asm("ex2.approx.ftz.f32 %0, %1;" : "=f"(y) : "f"(x)); return y;
}
__device__ __forceinline__ uint32_t smem_u32(const void* p) {
    uint32_t a;
    asm("{ .reg .u64 t; cvta.to.shared.u64 t, %1; cvt.u32.u64 %0, t; }" : "=r"(a) : "l"(p));
    return a;
}
__device__ __forceinline__ void cp_async16(uint32_t dst, const void* src) {
    asm volatile("cp.async.cg.shared.global [%0], [%1], 16;" :: "r"(dst), "l"(src) : "memory");
}
#define LDMX4(r, addr)                                                          \
    asm volatile("ldmatrix.sync.aligned.m8n8.x4.shared.b16 {%0,%1,%2,%3}, [%4];" \
                 : "=r"((r)[0]), "=r"((r)[1]), "=r"((r)[2]), "=r"((r)[3])        \
                 : "r"(addr))

// ---------------- prep ----------------
__global__ void wprep_kernel(const float* __restrict__ w) {
    __shared__ float sh[DIM];
    int t = threadIdx.x;
    float c = fminf(fmaxf(w[t], 0.0f), 2.0f);
    sh[t] = c;
    __syncthreads();
    for (int off = DIM / 2; off > 0; off >>= 1) {
        if (t < off) sh[t] += sh[t + off];
        __syncthreads();
    }
    d_wc[t] = c * ((float)DIM / sh[0]);
}

__global__ void rownorm_kernel(const float* __restrict__ x1, const float* __restrict__ x2) {
    __shared__ float sh[DIM];
    int b = blockIdx.x, t = threadIdx.x;
    float v;
    if (b < NPTS) v = d_wc[t] * x1[(size_t)b * DIM + t];
    else          v = x2[(size_t)(b - NPTS) * DIM + t];
    sh[t] = v * v;
    __syncthreads();
    for (int off = DIM / 2; off > 0; off >>= 1) {
        if (t < off) sh[t] += sh[t + off];
        __syncthreads();
    }
    float inv = 1.0f / (sqrtf(sh[0]) + 1e-12f);
    __half h = __float2half_rn(v * inv);
    if (b < NPTS) d_anh[(size_t)b * DIM + t] = h;
    else          d_bnh[(size_t)(b - NPTS) * DIM + t] = h;
}

__global__ void zero_kernel() {
    int i = blockIdx.x * blockDim.x + threadIdx.x;
    if (i < NPTS) {
        d_f[0][i] = 0.0f; d_g[0][i] = 0.0f;
        d_fxx[0][i] = 0.0f; d_gyy[0][i] = 0.0f;
    }
}

// ---------------- HMMA GEMM: C = A * B^T (+ transposed output CT) ----------------
__global__ void __launch_bounds__(256, 2) gemm_mma(const __half* __restrict__ A,
                                                   const __half* __restrict__ B,
                                                   __half* __restrict__ C,
                                                   __half* __restrict__ CT,
                                                   int sym) {
    extern __shared__ char smem[];
    const int btx = blockIdx.x, bty = blockIdx.y;
    if (sym && btx > bty) return;

    const uint32_t smem_base = smem_u32(smem);
    const int tid = threadIdx.x;
    const int wid = tid >> 5, lane = tid & 31;
    const int warp_m = wid >> 2, warp_n = wid & 3;
    const int rowBase = bty * 128;
    const int colBase = btx * 128;

    const int mat = lane >> 3, rin = lane & 7;
    const int a_row_in = (mat & 1) * 8 + rin;
    const int a_kh     = (mat >> 1) * 8;
    const int b_row_in = (mat >> 1) * 8 + rin;
    const int b_kh     = (mat & 1) * 8;

    float acc[4][4][4];
#pragma unroll
    for (int mi = 0; mi < 4; ++mi)
#pragma unroll
        for (int ni = 0; ni < 4; ++ni)
#pragma unroll
            for (int q = 0; q < 4; ++q) acc[mi][ni][q] = 0.0f;

#define ISSUE_CHUNK(c, b) do {                                                  \
        const __half* Asrc_ = A + (size_t)rowBase * DIM + (c) * KC;             \
        const __half* Bsrc_ = B + (size_t)colBase * DIM + (c) * KC;             \
        uint32_t Ab_ = smem_base + (b) * 32768;                                 \
        uint32_t Bb_ = Ab_ + 16384;                                             \
        _Pragma("unroll")                                                       \
        for (int q_ = 0; q_ < 4; ++q_) {                                        \
            int i_ = q_ * 256 + tid;                                            \
            int r_ = i_ >> 3, cw_ = i_ & 7;                                     \
            uint32_t off_ = r_ * 128 + (((uint32_t)(cw_ ^ (r_ & 7))) << 4);     \
            cp_async16(Ab_ + off_, Asrc_ + (size_t)r_ * DIM + cw_ * 8);         \
            cp_async16(Bb_ + off_, Bsrc_ + (size_t)r_ * DIM + cw_ * 8);         \
        }                                                                       \
        asm volatile("cp.async.commit_group;" ::: "memory");                    \
    } while (0)

    ISSUE_CHUNK(0, 0);
#pragma unroll
    for (int c = 0; c < NCHUNK; ++c) {
        if (c + 1 < NCHUNK) {
            ISSUE_CHUNK(c + 1, (c + 1) & 1);
            asm volatile("cp.async.wait_group 1;" ::: "memory");
        } else {
            asm volatile("cp.async.wait_group 0;" ::: "memory");
        }
        __syncthreads();
        uint32_t Ab = smem_base + (c & 1) * 32768;
        uint32_t Bb = Ab + 16384;
#pragma unroll
        for (int ks = 0; ks < 4; ++ks) {
            uint32_t bf[2][4];
#pragma unroll
            for (int p = 0; p < 2; ++p) {
                int nrow = warp_n * 32 + p * 16 + b_row_in;
                int kcol = ks * 16 + b_kh;
                uint32_t addr = Bb + nrow * 128 + ((uint32_t)((kcol >> 3) ^ (nrow & 7)) << 4);
                LDMX4(bf[p], addr);
            }
#pragma unroll
            for (int mi = 0; mi < 4; ++mi) {
                uint32_t af[4];
                int arow = warp_m * 64 + mi * 16 + a_row_in;
                int kcol = ks * 16 + a_kh;
                uint32_t addr = Ab + arow * 128 + ((uint32_t)((kcol >> 3) ^ (arow & 7)) << 4);
                LDMX4(af, addr);
#pragma unroll
                for (int ni = 0; ni < 4; ++ni) {
                    asm volatile(
                        "mma.sync.aligned.m16n8k16.row.col.f32.f16.f16.f32 "
                        "{%0,%1,%2,%3}, {%4,%5,%6,%7}, {%8,%9}, {%0,%1,%2,%3};"
                        : "+f"(acc[mi][ni][0]), "+f"(acc[mi][ni][1]),
                          "+f"(acc[mi][ni][2]), "+f"(acc[mi][ni][3])
                        : "r"(af[0]), "r"(af[1]), "r"(af[2]), "r"(af[3]),
                          "r"(bf[ni >> 1][(ni & 1) * 2]), "r"(bf[ni >> 1][(ni & 1) * 2 + 1]));
                }
            }
        }
        __syncthreads();
    }
#undef ISSUE_CHUNK

    __half* stage = (__half*)smem;
#pragma unroll
    for (int mi = 0; mi < 4; ++mi)
#pragma unroll
        for (int ni = 0; ni < 4; ++ni) {
            int row = warp_m * 64 + mi * 16 + (lane >> 2);
            int col = warp_n * 32 + ni * 8 + 2 * (lane & 3);
            __half2 lo = __floats2half2_rn(acc[mi][ni][0], acc[mi][ni][1]);
            __half2 hi = __floats2half2_rn(acc[mi][ni][2], acc[mi][ni][3]);
            *(__half2*)(stage + row * 136 + col)       = lo;
            *(__half2*)(stage + (row + 8) * 136 + col) = hi;
        }
    __syncthreads();
#pragma unroll
    for (int i = tid; i < 2048; i += 256) {
        int r = i >> 4, ch = i & 15;
        uint4 v = *(uint4*)(stage + r * 136 + ch * 8);
        *(uint4*)(C + (size_t)(rowBase + r) * NPTS + colBase + ch * 8) = v;
    }

    if (!(sym && btx == bty)) {
        __syncthreads();
#pragma unroll
        for (int mi = 0; mi < 4; ++mi)
#pragma unroll
            for (int ni = 0; ni < 4; ++ni) {
                int row = warp_m * 64 + mi * 16 + (lane >> 2);
                int col = warp_n * 32 + ni * 8 + 2 * (lane & 3);
                stage[col * 136 + row]           = __float2half_rn(acc[mi][ni][0]);
                stage[(col + 1) * 136 + row]     = __float2half_rn(acc[mi][ni][1]);
                stage[col * 136 + row + 8]       = __float2half_rn(acc[mi][ni][2]);
                stage[(col + 1) * 136 + row + 8] = __float2half_rn(acc[mi][ni][3]);
            }
        __syncthreads();
#pragma unroll
        for (int i = tid; i < 2048; i += 256) {
            int r = i >> 4, ch = i & 15;
            uint4 v = *(uint4*)(stage + r * 136 + ch * 8);
            *(uint4*)(CT + (size_t)(colBase + r) * NPTS + rowBase + ch * 8) = v;
        }
    }
}

// ---------------- dense softmin: cp.async-staged, 512 threads, RPB rows ----------------
struct SMArgs {
    const __half* G[4];
    const float*  pot[4];
    const float*  oldpot[4];
    float*        out[4];
    int           avg[4];
};

__global__ void __launch_bounds__(SOFT_T) softmin4(SMArgs args, float eps) {
    extern __shared__ char smg[];               // RPB * 16 KB
    const uint32_t smg_u = smem_u32(smg);
    const int var  = blockIdx.y;
    const int row0 = blockIdx.x * RPB;
    const int tid  = threadIdx.x;
    const int lane = tid & 31, wid = tid >> 5;  // 16 warps

    const float L2E = 1.4426950408889634f;
    const float c1 = L2E / eps;
    const float c0 = -c1;

    // ---- issue all G copies (64 KB, 8 x 16B per thread) ----
    const __half* Gbase = args.G[var];
#pragma unroll
    for (int r = 0; r < RPB; ++r) {
        const __half* Gr = Gbase + (size_t)(row0 + r) * NPTS;
#pragma unroll
        for (int q = 0; q < 2; ++q) {
            int idx = q * SOFT_T + tid;         // 0..1023 16B-chunks
            cp_async16(smg_u + r * 16384 + idx * 16, Gr + idx * 8);
        }
    }
    asm volatile("cp.async.commit_group;" ::: "memory");

    // ---- fold pot while copies fly: pp[k] = (pot_k - 1) * c1 ----
    const float* pot = args.pot[var];
    float pp[16];
#pragma unroll
    for (int it = 0; it < 2; ++it) {
        int idx = it * SOFT_T + tid;
        float4 a = ((const float4*)pot)[2 * idx];
        float4 b = ((const float4*)pot)[2 * idx + 1];
        pp[8 * it + 0] = fmaf(a.x, c1, c0); pp[8 * it + 1] = fmaf(a.y, c1, c0);
        pp[8 * it + 2] = fmaf(a.z, c1, c0); pp[8 * it + 3] = fmaf(a.w, c1, c0);
        pp[8 * it + 4] = fmaf(b.x, c1, c0); pp[8 * it + 5] = fmaf(b.y, c1, c0);
        pp[8 * it + 6] = fmaf(b.z, c1, c0); pp[8 * it + 7] = fmaf(b.w, c1, c0);
    }

    asm volatile("cp.async.wait_group 0;" ::: "memory");

    __shared__ float sA[RPB][16];
    __shared__ float sS[RPB][16];

    // ---- pass A: per-row max (from SMEM) ----
    float wtm[RPB];
#pragma unroll
    for (int r = 0; r < RPB; ++r) {
        float tm = -INFINITY;
#pragma unroll
        for (int it = 0; it < 2; ++it) {
            uint4 q = *(const uint4*)(smg + r * 16384 + (it * SOFT_T + tid) * 16);
            float2 g0 = __half22float2(*(const __half2*)&q.x);
            float2 g1 = __half22float2(*(const __half2*)&q.y);
            float2 g2 = __half22float2(*(const __half2*)&q.z);
            float2 g3 = __half22float2(*(const __half2*)&q.w);
            float v0 = fmaf(g0.x, c1, pp[8 * it + 0]);
            float v1 = fmaf(g0.y, c1, pp[8 * it + 1]);
            float v2 = fmaf(g1.x, c1, pp[8 * it + 2]);
            float v3 = fmaf(g1.y, c1, pp[8 * it + 3]);
            float v4 = fmaf(g2.x, c1, pp[8 * it + 4]);
            float v5 = fmaf(g2.y, c1, pp[8 * it + 5]);
            float v6 = fmaf(g3.x, c1, pp[8 * it + 6]);
            float v7 = fmaf(g3.y, c1, pp[8 * it + 7]);
            tm = fmaxf(tm, fmaxf(fmaxf(fmaxf(v0, v1), fmaxf(v2, v3)),
                                 fmaxf(fmaxf(v4, v5), fmaxf(v6, v7))));
        }
#pragma unroll
        for (int off = 16; off > 0; off >>= 1)
            tm = fmaxf(tm, __shfl_xor_sync(0xffffffffu, tm, off));
        wtm[r] = tm;
        if (lane == 0) sA[r][wid] = tm;
    }
    __syncthreads();
    float M[RPB];
#pragma unroll
    for (int r = 0; r < RPB; ++r) {
        float m = sA[r][0];
#pragma unroll
        for (int i = 1; i < 16; ++i) m = fmaxf(m, sA[r][i]);
        M[r] = m;
    }

    // ---- pass B: exp-sum from SMEM, only contributing warps ----
#pragma unroll
    for (int r = 0; r < RPB; ++r) {
        float s = 0.0f;
        if (wtm[r] >= M[r] - 40.0f) {
            float Mr = M[r];
            float s0 = 0.f, s1 = 0.f, s2 = 0.f, s3 = 0.f;
#pragma unroll
            for (int it = 0; it < 2; ++it) {
                uint4 q = *(const uint4*)(smg + r * 16384 + (it * SOFT_T + tid) * 16);
                float2 g0 = __half22float2(*(const __half2*)&q.x);
                float2 g1 = __half22float2(*(const __half2*)&q.y);
                float2 g2 = __half22float2(*(const __half2*)&q.z);
                float2 g3 = __half22float2(*(const __half2*)&q.w);
                s0 += ex2f_fast(fmaf(g0.x, c1, pp[8 * it + 0]) - Mr);
                s1 += ex2f_fast(fmaf(g0.y, c1, pp[8 * it + 1]) - Mr);
                s2 += ex2f_fast(fmaf(g1.x, c1, pp[8 * it + 2]) - Mr);
                s3 += ex2f_fast(fmaf(g1.y, c1, pp[8 * it + 3]) - Mr);
                s0 += ex2f_fast(fmaf(g2.x, c1, pp[8 * it + 4]) - Mr);
                s1 += ex2f_fast(fmaf(g2.y, c1, pp[8 * it + 5]) - Mr);
                s2 += ex2f_fast(fmaf(g3.x, c1, pp[8 * it + 6]) - Mr);
                s3 += ex2f_fast(fmaf(g3.y, c1, pp[8 * it + 7]) - Mr);
            }
            s = (s0 + s1) + (s2 + s3);
        }
#pragma unroll
        for (int off = 16; off > 0; off >>= 1)
            s += __shfl_xor_sync(0xffffffffu, s, off);
        if (lane == 0) sS[r][wid] = s;
    }
    __syncthreads();

    if (tid < RPB) {
        int r = tid;
        float S = 0.0f;
#pragma unroll
        for (int i = 0; i < 16; ++i) S += sS[r][i];
        const float LOGW = -9.010913347279288f;   // -log(8192)
        const float LN2  = 0.6931471805599453f;
        float lse = (M[r] + log2f(S)) * LN2;
        float res = -eps * (LOGW + lse);
        if (args.avg[var]) res = 0.5f * (args.oldpot[var][row0 + r] + res);
        args.out[var][row0 + r] = res;
    }
}

// ---------------- final reduction ----------------
__global__ void final_reduce(float* __restrict__ out) {
    __shared__ float sh[1024];
    int t = threadIdx.x;
    float s = 0.0f;
    for (int i = t; i < NPTS; i += 1024)
        s += (d_ffin[i] - d_xfin[i]) + (d_gfin[i] - d_yfin[i]);
    sh[t] = s;
    __syncthreads();
    for (int off = 512; off > 0; off >>= 1) {
        if (t < off) sh[t] += sh[t + off];
        __syncthreads();
    }
    if (t == 0) out[0] = sh[0] / (float)NPTS;
}

// ---------------- host ----------------
static void* symaddr(const void* sym) {
    void* p = nullptr;
    cudaGetSymbolAddress(&p, sym);
    return p;
}

#define GEMM_SMEM 65536

extern "C" void kernel_launch(void* const* d_in, const int* in_sizes, int n_in,
                              void* d_out, int out_size) {
    const float* x1 = (const float*)d_in[0];
    const float* x2 = (const float*)d_in[1];
    const float* w  = (const float*)d_in[2];

    __half* an  = (__half*)symaddr(d_anh);
    __half* bn  = (__half*)symaddr(d_bnh);
    __half* Gxy = (__half*)symaddr(d_Gxy);
    __half* Gyx = (__half*)symaddr(d_Gyx);
    __half* Gxx = (__half*)symaddr(d_Gxx);
    __half* Gyy = (__half*)symaddr(d_Gyy);
    float* fb  = (float*)symaddr(d_f);
    float* gb  = (float*)symaddr(d_g);
    float* xb  = (float*)symaddr(d_fxx);
    float* yb  = (float*)symaddr(d_gyy);
    float* ffin = (float*)symaddr(d_ffin);
    float* gfin = (float*)symaddr(d_gfin);
    float* xfin = (float*)symaddr(d_xfin);
    float* yfin = (float*)symaddr(d_yfin);

    cudaFuncSetAttribute(gemm_mma, cudaFuncAttributeMaxDynamicSharedMemorySize, GEMM_SMEM);
    cudaFuncSetAttribute(softmin4, cudaFuncAttributeMaxDynamicSharedMemorySize, SM_SOFTMIN);

    wprep_kernel<<<1, DIM>>>(w);
    rownorm_kernel<<<2 * NPTS, DIM>>>(x1, x2);
    zero_kernel<<<NPTS / 256, 256>>>();

    dim3 ggrid(NPTS / 128, NPTS / 128);
    gemm_mma<<<ggrid, 256, GEMM_SMEM>>>(an, bn, Gxy, Gyx, 0);
    gemm_mma<<<ggrid, 256, GEMM_SMEM>>>(an, an, Gxx, Gxx, 1);
    gemm_mma<<<ggrid, 256, GEMM_SMEM>>>(bn, bn, Gyy, Gyy, 1);

    const float eps_list[10] = {4.0f, 1.0f, 0.25f, 0.0625f, 0.015625f,
                                0.00390625f, 0.0025f, 0.0025f, 0.0025f, 0.0025f};
    dim3 sgrid(NPTS / RPB, 4);
    int cur = 0;
    for (int i = 0; i < 10; ++i) {
        float eps = eps_list[i];
        int nxt = 1 - cur;
        SMArgs a;
        a.G[0] = Gxx;  a.pot[0] = xb + cur * NPTS; a.oldpot[0] = xb + cur * NPTS; a.out[0] = xb + nxt * NPTS; a.avg[0] = 1;
        a.G[1] = Gyy;  a.pot[1] = yb + cur * NPTS; a.oldpot[1] = yb + cur * NPTS; a.out[1] = yb + nxt * NPTS; a.avg[1] = 1;
        a.G[2] = Gxy;  a.pot[2] = gb + cur * NPTS; a.oldpot[2] = nullptr;         a.out[2] = fb + nxt * NPTS; a.avg[2] = 0;
        a.G[3] = Gyx;  a.pot[3] = fb + cur * NPTS; a.oldpot[3] = nullptr;         a.out[3] = gb + nxt * NPTS; a.avg[3] = 0;
        softmin4<<<sgrid, SOFT_T, SM_SOFTMIN>>>(a, eps);
        cur = nxt;
    }

    const float epsF = 0.0025f;
    {
        SMArgs a;
        a.G[0] = Gxy; a.pot[0] = gb + cur * NPTS; a.oldpot[0] = nullptr; a.out[0] = ffin; a.avg[0] = 0;
        a.G[1] = Gyx; a.pot[1] = fb + cur * NPTS; a.oldpot[1] = nullptr; a.out[1] = gfin; a.avg[1] = 0;
        a.G[2] = Gxx; a.pot[2] = xb + cur * NPTS; a.oldpot[2] = nullptr; a.out[2] = xfin; a.avg[2] = 0;
        a.G[3] = Gyy; a.pot[3] = yb + cur * NPTS; a.oldpot[3] = nullptr; a.out[3] = yfin; a.avg[3] = 0;
        softmin4<<<sgrid, SOFT_T, SM_SOFTMIN>>>(a, epsF);
    }

    final_reduce<<<1, 1024>>>((float*)d_out);
}